// round 2
// baseline (speedup 1.0000x reference)
#include <cuda_runtime.h>
#include <math.h>

// ---------------- problem constants ----------------
#define BATCH 16
#define CIN   256
#define EDIM  256
#define HWSZ  4096           // 64*64
#define NPIX  65536          // BATCH*HWSZ
#define RNUM  365
#define RPAD  384            // 12 * 32
#define NMODE 2

#define TOT1     ((size_t)BATCH * RNUM * HWSZ)   // 23,920,640
#define OFF_CLS    ((size_t)0)
#define OFF_CLSNEG (TOT1)
#define OFF_DIST   (2*TOT1)
#define OFF_DNEG   (3*TOT1)
#define OFF_PORI   (5*TOT1)

// ---------------- scratch (static device memory, no runtime alloc) ----------------
__device__ float g_emb[(size_t)NPIX * EDIM];        // 64 MB, normalized embeddings [P][E]
__device__ float g_reps[3 * RPAD * EDIM];           // [mode][r][e], mode 0=pos,1=neg0,2=neg1

// ---------------- f32x2 helpers (Blackwell packed fp32) ----------------
__device__ __forceinline__ unsigned long long f2_pack(float lo, float hi) {
    unsigned long long r;
    asm("mov.b64 %0, {%1,%2};" : "=l"(r) : "f"(lo), "f"(hi));
    return r;
}
__device__ __forceinline__ void f2_unpack(unsigned long long v, float& lo, float& hi) {
    asm("mov.b64 {%0,%1}, %2;" : "=f"(lo), "=f"(hi) : "l"(v));
}
__device__ __forceinline__ void f2_fma(unsigned long long& d, unsigned long long a, unsigned long long b) {
    asm("fma.rn.f32x2 %0, %1, %2, %0;" : "+l"(d) : "l"(a), "l"(b));
}

// =====================================================================
// Kernel 1: build the 3 rep matrices (pos / neg0 / neg1), L2-normalized.
// grid 48 blocks x 256 threads; block handles 8 r rows (incl. zero pad rows).
// =====================================================================
__global__ __launch_bounds__(256) void prep_reps_kernel(
    const float* __restrict__ reps,      // [365][256] (already unit norm)
    const float* __restrict__ negw,      // [512][256]
    const float* __restrict__ negb)      // [512]
{
    __shared__ float s_rep[8][256];
    __shared__ float s_off[8][512];
    const int tid = threadIdx.x;
    const int r0 = blockIdx.x * 8;
    const int w = tid >> 5, lane = tid & 31;

    #pragma unroll
    for (int i = 0; i < 8; i++) {
        int r = r0 + i;
        s_rep[i][tid] = (r < RNUM) ? reps[r * 256 + tid] : 0.f;
    }
    __syncthreads();

    // neg_offset[r][j] = sum_k |rep[r][k]| * W[j][k] + b[j]; warp w handles 64 j's
    for (int jj = 0; jj < 64; jj++) {
        int j = w * 64 + jj;
        float part[8];
        #pragma unroll
        for (int rl = 0; rl < 8; rl++) part[rl] = 0.f;
        #pragma unroll
        for (int i2 = 0; i2 < 8; i2++) {
            int k = lane + 32 * i2;
            float wv = negw[j * 256 + k];
            #pragma unroll
            for (int rl = 0; rl < 8; rl++) part[rl] += wv * fabsf(s_rep[rl][k]);
        }
        #pragma unroll
        for (int off = 16; off > 0; off >>= 1) {
            #pragma unroll
            for (int rl = 0; rl < 8; rl++)
                part[rl] += __shfl_xor_sync(0xffffffffu, part[rl], off);
        }
        if (lane < 8) s_off[lane][j] = part[lane] + negb[j];
    }
    __syncthreads();

    // each warp handles (i,m) pairs: w -> (i=w,m=0), w+8 -> (i=w,m=1)
    #pragma unroll
    for (int pi = 0; pi < 2; pi++) {
        int pair = w + pi * 8;
        int i = pair & 7, m = pair >> 3;
        float vals[8];
        float ss = 0.f;
        #pragma unroll
        for (int q = 0; q < 8; q++) {
            int e = lane + 32 * q;
            float rv = s_rep[i][e];
            float sg = (rv > 0.f ? 1.f : 0.f) - (rv < 0.f ? 1.f : 0.f);
            float v = (s_off[i][m * 256 + e] + fabsf(rv)) * sg;
            vals[q] = v;
            ss += v * v;
        }
        #pragma unroll
        for (int off = 16; off > 0; off >>= 1) ss += __shfl_xor_sync(0xffffffffu, ss, off);
        float inv = 1.f / fmaxf(sqrtf(ss), 1e-12f);
        int r = r0 + i;
        #pragma unroll
        for (int q = 0; q < 8; q++)
            g_reps[((1 + m) * RPAD + r) * 256 + lane + 32 * q] = vals[q] * inv;
    }
    // positive reps (already unit norm); pad rows are zeros
    #pragma unroll
    for (int i = 0; i < 8; i++)
        g_reps[(0 * RPAD + (r0 + i)) * 256 + tid] = s_rep[i][tid];
}

// =====================================================================
// Kernel 2: 1x1 conv + bias + L2 normalize over channels.
// grid 1024 blocks x 256 threads; block = 64 pixels x all 256 outputs.
// thread (ty,tx): ty in [0,8) -> 8 pixels; tx in [0,32)=lane -> 8 e's.
// =====================================================================
__global__ __launch_bounds__(256) void conv_norm_kernel(
    const float* __restrict__ x,     // [B][C][HW]
    const float* __restrict__ W,     // [E][C]
    const float* __restrict__ bias)  // [E]
{
    __shared__ float sA[16 * 64];     // [k][px]
    __shared__ float sB[16 * 260];    // [k][e] padded
    __shared__ float sbias[256];

    const int t = threadIdx.x;
    const int tx = t & 31, ty = t >> 5;
    const int p0 = blockIdx.x * 64;
    const int bimg = p0 >> 12;
    const int hw0 = p0 & 4095;

    sbias[t] = bias[t];

    unsigned long long acc[4][8];
    #pragma unroll
    for (int i = 0; i < 4; i++)
        #pragma unroll
        for (int e = 0; e < 8; e++) acc[i][e] = 0ull;

    const int pxl = t & 63, kb = t >> 6;   // sA loader coords
    const int kk = t & 15, eb = t >> 4;    // sB loader coords

    float rxA[4], rxB[16];
    // prologue load chunk 0
    #pragma unroll
    for (int i = 0; i < 4; i++)
        rxA[i] = x[((size_t)bimg * 256 + (kb + 4 * i)) * 4096 + hw0 + pxl];
    #pragma unroll
    for (int i = 0; i < 16; i++)
        rxB[i] = W[(size_t)(eb + 16 * i) * 256 + kk];

    for (int c0 = 0; c0 < 256; c0 += 16) {
        __syncthreads();
        #pragma unroll
        for (int i = 0; i < 4; i++) sA[(kb + 4 * i) * 64 + pxl] = rxA[i];
        #pragma unroll
        for (int i = 0; i < 16; i++) sB[kk * 260 + eb + 16 * i] = rxB[i];
        __syncthreads();
        if (c0 + 16 < 256) {
            int c1 = c0 + 16;
            #pragma unroll
            for (int i = 0; i < 4; i++)
                rxA[i] = x[((size_t)bimg * 256 + c1 + (kb + 4 * i)) * 4096 + hw0 + pxl];
            #pragma unroll
            for (int i = 0; i < 16; i++)
                rxB[i] = W[(size_t)(eb + 16 * i) * 256 + c1 + kk];
        }
        #pragma unroll
        for (int k = 0; k < 16; k++) {
            const float* sak = &sA[k * 64 + ty * 8];
            unsigned long long a0 = *(const unsigned long long*)(sak + 0);
            unsigned long long a1 = *(const unsigned long long*)(sak + 2);
            unsigned long long a2 = *(const unsigned long long*)(sak + 4);
            unsigned long long a3 = *(const unsigned long long*)(sak + 6);
            const float* sbk = &sB[k * 260 + tx * 8];
            float4 bv0 = *(const float4*)(sbk);
            float4 bv1 = *(const float4*)(sbk + 4);
            float bf[8] = {bv0.x, bv0.y, bv0.z, bv0.w, bv1.x, bv1.y, bv1.z, bv1.w};
            #pragma unroll
            for (int e = 0; e < 8; e++) {
                unsigned long long d = f2_pack(bf[e], bf[e]);
                f2_fma(acc[0][e], a0, d);
                f2_fma(acc[1][e], a1, d);
                f2_fma(acc[2][e], a2, d);
                f2_fma(acc[3][e], a3, d);
            }
        }
    }

    // epilogue: bias, norm over all 256 e (warp = 32 tx-lanes share same 8 px)
    float v[8][8];
    #pragma unroll
    for (int i = 0; i < 4; i++)
        #pragma unroll
        for (int e = 0; e < 8; e++)
            f2_unpack(acc[i][e], v[2 * i][e], v[2 * i + 1][e]);
    #pragma unroll
    for (int pp = 0; pp < 8; pp++)
        #pragma unroll
        for (int e = 0; e < 8; e++) v[pp][e] += sbias[tx * 8 + e];

    float part[8];
    #pragma unroll
    for (int pp = 0; pp < 8; pp++) {
        float s = 0.f;
        #pragma unroll
        for (int e = 0; e < 8; e++) s += v[pp][e] * v[pp][e];
        part[pp] = s;
    }
    #pragma unroll
    for (int off = 16; off > 0; off >>= 1)
        #pragma unroll
        for (int pp = 0; pp < 8; pp++)
            part[pp] += __shfl_xor_sync(0xffffffffu, part[pp], off);

    #pragma unroll
    for (int pp = 0; pp < 8; pp++) {
        float inv = 1.f / fmaxf(sqrtf(part[pp]), 1e-12f);
        float* dst = &g_emb[(size_t)(p0 + ty * 8 + pp) * 256 + tx * 8];
        *(float4*)(dst)     = make_float4(v[pp][0] * inv, v[pp][1] * inv, v[pp][2] * inv, v[pp][3] * inv);
        *(float4*)(dst + 4) = make_float4(v[pp][4] * inv, v[pp][5] * inv, v[pp][6] * inv, v[pp][7] * inv);
    }
}

// =====================================================================
// Kernel 3: main fused GEMM (dots vs pos/neg0/neg1) + epilogue.
// grid (512, 12) x 256 threads. Tile: 128 px x 32 r (x3 modes).
// thread (tx,ty): tx in [0,16) -> 2 r's; ty in [0,16) -> 8 consecutive px.
// =====================================================================
__global__ __launch_bounds__(256) void dml_main_kernel(float* __restrict__ out)
{
    __shared__ float sA[16 * 132];   // [k][px] padded
    __shared__ float sB[16 * 98];    // [k][col], col = mode*32 + rl, padded

    const int t = threadIdx.x;
    const int tx = t & 15, ty = t >> 4;
    const int p0 = (int)blockIdx.x * 128;
    const int r1 = (int)blockIdx.y * 32;
    const int bimg = p0 >> 12;
    const int hw0 = p0 & 4095;

    unsigned long long acc[4][6];
    #pragma unroll
    for (int i = 0; i < 4; i++)
        #pragma unroll
        for (int j = 0; j < 6; j++) acc[i][j] = 0ull;

    const int kA = t & 15;
    const int gb = t >> 4;   // loader row base

    float rA[8], rB[6];
    // prologue chunk 0
    #pragma unroll
    for (int i = 0; i < 8; i++)
        rA[i] = g_emb[(size_t)(p0 + gb + 16 * i) * 256 + kA];
    #pragma unroll
    for (int i = 0; i < 6; i++) {
        int row = gb + 16 * i;              // 0..95
        int mode = row >> 5, rl = row & 31;
        rB[i] = g_reps[(mode * RPAD + r1 + rl) * 256 + kA];
    }

    for (int c0 = 0; c0 < 256; c0 += 16) {
        __syncthreads();
        #pragma unroll
        for (int i = 0; i < 8; i++) sA[kA * 132 + gb + 16 * i] = rA[i];
        #pragma unroll
        for (int i = 0; i < 6; i++) sB[kA * 98 + gb + 16 * i] = rB[i];
        __syncthreads();
        if (c0 + 16 < 256) {
            int c1 = c0 + 16;
            #pragma unroll
            for (int i = 0; i < 8; i++)
                rA[i] = g_emb[(size_t)(p0 + gb + 16 * i) * 256 + c1 + kA];
            #pragma unroll
            for (int i = 0; i < 6; i++) {
                int row = gb + 16 * i;
                int mode = row >> 5, rl = row & 31;
                rB[i] = g_reps[(mode * RPAD + r1 + rl) * 256 + c1 + kA];
            }
        }
        #pragma unroll
        for (int k = 0; k < 16; k++) {
            const float* sak = &sA[k * 132 + ty * 8];
            unsigned long long a0 = *(const unsigned long long*)(sak + 0);
            unsigned long long a1 = *(const unsigned long long*)(sak + 2);
            unsigned long long a2 = *(const unsigned long long*)(sak + 4);
            unsigned long long a3 = *(const unsigned long long*)(sak + 6);
            const float* sbk = &sB[k * 98 + 2 * tx];
            float b00 = sbk[0],  b01 = sbk[1];
            float b10 = sbk[32], b11 = sbk[33];
            float b20 = sbk[64], b21 = sbk[65];
            unsigned long long d;
            d = f2_pack(b00, b00); f2_fma(acc[0][0], a0, d); f2_fma(acc[1][0], a1, d); f2_fma(acc[2][0], a2, d); f2_fma(acc[3][0], a3, d);
            d = f2_pack(b01, b01); f2_fma(acc[0][1], a0, d); f2_fma(acc[1][1], a1, d); f2_fma(acc[2][1], a2, d); f2_fma(acc[3][1], a3, d);
            d = f2_pack(b10, b10); f2_fma(acc[0][2], a0, d); f2_fma(acc[1][2], a1, d); f2_fma(acc[2][2], a2, d); f2_fma(acc[3][2], a3, d);
            d = f2_pack(b11, b11); f2_fma(acc[0][3], a0, d); f2_fma(acc[1][3], a1, d); f2_fma(acc[2][3], a2, d); f2_fma(acc[3][3], a3, d);
            d = f2_pack(b20, b20); f2_fma(acc[0][4], a0, d); f2_fma(acc[1][4], a1, d); f2_fma(acc[2][4], a2, d); f2_fma(acc[3][4], a3, d);
            d = f2_pack(b21, b21); f2_fma(acc[0][5], a0, d); f2_fma(acc[1][5], a1, d); f2_fma(acc[2][5], a2, d); f2_fma(acc[3][5], a3, d);
        }
    }

    // -------- epilogue --------
    const int hwb = hw0 + ty * 8;
    #pragma unroll
    for (int rr = 0; rr < 2; rr++) {
        int r = r1 + 2 * tx + rr;
        if (r >= RNUM) continue;
        float fd[8], f0o[8], f1o[8], fcn[8], fpo[8], fpr[8];
        #pragma unroll
        for (int i = 0; i < 4; i++) {
            float pl, ph, n0l, n0h, n1l, n1h;
            f2_unpack(acc[i][0 + rr], pl, ph);
            f2_unpack(acc[i][2 + rr], n0l, n0h);
            f2_unpack(acc[i][4 + rr], n1l, n1h);
            #pragma unroll
            for (int h = 0; h < 2; h++) {
                int px = 2 * i + h;
                float dotp = h ? ph : pl;
                float dot0 = h ? n0h : n0l;
                float dot1 = h ? n1h : n1l;
                float dp2 = fmaxf(2.f - 2.f * dotp, 0.f);
                float d02 = fmaxf(2.f - 2.f * dot0, 0.f);
                float d12 = fmaxf(2.f - 2.f * dot1, 0.f);
                float dp = sqrtf(dp2);
                float dmin2 = fminf(d02, d12);
                fd[px]  = dp;
                f0o[px] = sqrtf(d02);
                f1o[px] = sqrtf(d12);
                fcn[px] = __expf(-2.f * dmin2);
                fpo[px] = __expf(-2.f * dp2);
                float tt = dp + 0.3f * (2.f - sqrtf(dmin2));
                fpr[px] = __expf(-2.f * tt * tt);
            }
        }
        size_t bro  = (size_t)bimg * RNUM + r;
        size_t base = bro * HWSZ + hwb;
        float* o;
        o = out + OFF_DIST + base;
        *(float4*)(o)     = make_float4(fd[0], fd[1], fd[2], fd[3]);
        *(float4*)(o + 4) = make_float4(fd[4], fd[5], fd[6], fd[7]);
        o = out + OFF_CLS + base;
        *(float4*)(o)     = make_float4(fpr[0], fpr[1], fpr[2], fpr[3]);
        *(float4*)(o + 4) = make_float4(fpr[4], fpr[5], fpr[6], fpr[7]);
        o = out + OFF_CLSNEG + base;
        *(float4*)(o)     = make_float4(fcn[0], fcn[1], fcn[2], fcn[3]);
        *(float4*)(o + 4) = make_float4(fcn[4], fcn[5], fcn[6], fcn[7]);
        o = out + OFF_PORI + base;
        *(float4*)(o)     = make_float4(fpo[0], fpo[1], fpo[2], fpo[3]);
        *(float4*)(o + 4) = make_float4(fpo[4], fpo[5], fpo[6], fpo[7]);
        size_t bn = bro * 2 * HWSZ + hwb;
        o = out + OFF_DNEG + bn;
        *(float4*)(o)     = make_float4(f0o[0], f0o[1], f0o[2], f0o[3]);
        *(float4*)(o + 4) = make_float4(f0o[4], f0o[5], f0o[6], f0o[7]);
        o = out + OFF_DNEG + bn + HWSZ;
        *(float4*)(o)     = make_float4(f1o[0], f1o[1], f1o[2], f1o[3]);
        *(float4*)(o + 4) = make_float4(f1o[4], f1o[5], f1o[6], f1o[7]);
    }
}

// =====================================================================
// Kernel 4: cls_score normalization: out_cls[b,r,hw] /= sum_r out_cls[b,r,hw]
// =====================================================================
__global__ __launch_bounds__(256) void norm_pass_kernel(float* __restrict__ out)
{
    int p = blockIdx.x * 256 + threadIdx.x;   // 65536 threads
    int bimg = p >> 12, hw = p & 4095;
    size_t base = ((size_t)bimg * RNUM) * HWSZ + hw + OFF_CLS;
    float s = 0.f;
    #pragma unroll 8
    for (int r = 0; r < RNUM; r++) s += out[base + (size_t)r * HWSZ];
    float inv = 1.f / s;
    #pragma unroll 8
    for (int r = 0; r < RNUM; r++) out[base + (size_t)r * HWSZ] *= inv;
}

// =====================================================================
extern "C" void kernel_launch(void* const* d_in, const int* in_sizes, int n_in,
                              void* d_out, int out_size)
{
    (void)in_sizes; (void)n_in; (void)out_size;
    const float* x      = (const float*)d_in[0];
    const float* conv_w = (const float*)d_in[1];
    const float* conv_b = (const float*)d_in[2];
    const float* reps   = (const float*)d_in[3];
    const float* neg_w  = (const float*)d_in[4];
    const float* neg_b  = (const float*)d_in[5];
    float* out = (float*)d_out;

    prep_reps_kernel<<<48, 256>>>(reps, neg_w, neg_b);
    conv_norm_kernel<<<1024, 256>>>(x, conv_w, conv_b);
    dml_main_kernel<<<dim3(512, 12), 256>>>(out);
    norm_pass_kernel<<<256, 256>>>(out);
}

// round 4
// speedup vs baseline: 1.7914x; 1.7914x over previous
#include <cuda_runtime.h>
#include <cuda_bf16.h>
#include <cstdint>
#include <math.h>

// ---------------- problem constants ----------------
#define BATCH 16
#define EDIM  256
#define HWSZ  4096
#define NPIX  65536
#define RNUM  365
#define EK    768            // split-K: A'=[hi|lo|hi], B'=[hi|hi|lo]
#define NT_R  32             // r per tile
#define NCOLS 96             // 3 modes * 32 r
#define NTILES 12            // 384 / 32
#define MPX   128            // pixels per CTA

#define TOT1     ((size_t)BATCH * RNUM * HWSZ)
#define OFF_CLS    ((size_t)0)
#define OFF_CLSNEG (TOT1)
#define OFF_DIST   (2*TOT1)
#define OFF_DNEG   (3*TOT1)
#define OFF_PORI   (5*TOT1)

// ---------------- static device scratch ----------------
__device__ __nv_bfloat16 g_embA[(size_t)NPIX * EK];         // 96 MB
__device__ __nv_bfloat16 g_B[(size_t)NTILES * NCOLS * EK];  // 1.7 MB
__device__ float g_part[NTILES][NPIX];
__device__ float g_sum[NPIX];

// ---------------- helpers ----------------
__device__ __forceinline__ unsigned long long f2_pack(float lo, float hi) {
    unsigned long long r;
    asm("mov.b64 %0, {%1,%2};" : "=l"(r) : "f"(lo), "f"(hi));
    return r;
}
__device__ __forceinline__ void f2_unpack(unsigned long long v, float& lo, float& hi) {
    asm("mov.b64 {%0,%1}, %2;" : "=f"(lo), "=f"(hi) : "l"(v));
}
__device__ __forceinline__ void f2_fma(unsigned long long& d, unsigned long long a, unsigned long long b) {
    asm("fma.rn.f32x2 %0, %1, %2, %0;" : "+l"(d) : "l"(a), "l"(b));
}
__device__ __forceinline__ uint32_t pk_bf2(__nv_bfloat16 a, __nv_bfloat16 b) {
    unsigned short ua = __bfloat16_as_ushort(a), ub = __bfloat16_as_ushort(b);
    return (uint32_t)ua | ((uint32_t)ub << 16);
}
__device__ __forceinline__ uint32_t smem_u32(const void* p) {
    uint32_t a;
    asm("{ .reg .u64 t; cvta.to.shared.u64 t, %1; cvt.u32.u64 %0, t; }" : "=r"(a) : "l"(p));
    return a;
}

#define LDSM_X4(r0, r1, r2, r3, addr)                                          \
    asm volatile("ldmatrix.sync.aligned.m8n8.x4.shared.b16 {%0,%1,%2,%3}, [%4];" \
        : "=r"(r0), "=r"(r1), "=r"(r2), "=r"(r3) : "r"(addr))

#define MMA_BF16(c, a, b0, b1)                                                 \
    asm volatile("mma.sync.aligned.m16n8k16.row.col.f32.bf16.bf16.f32 "        \
        "{%0,%1,%2,%3}, {%4,%5,%6,%7}, {%8,%9}, {%0,%1,%2,%3};"                \
        : "+f"((c)[0]), "+f"((c)[1]), "+f"((c)[2]), "+f"((c)[3])               \
        : "r"((a)[0]), "r"((a)[1]), "r"((a)[2]), "r"((a)[3]), "r"(b0), "r"(b1))

// =====================================================================
// Kernel 1: build B' (pos / neg0 / neg1, normalized, split bf16).
// grid 48 x 256; block handles 8 r rows (incl. zero pad to 384).
// B layout: [tile(12)][col(96) = mode*32 + (r&31)][EK]
// =====================================================================
__global__ __launch_bounds__(256) void prep_reps_kernel(
    const float* __restrict__ reps,
    const float* __restrict__ negw,
    const float* __restrict__ negb)
{
    __shared__ float s_rep[8][256];
    __shared__ float s_off[8][512];
    const int tid = threadIdx.x;
    const int r0 = blockIdx.x * 8;
    const int w = tid >> 5, lane = tid & 31;

    #pragma unroll
    for (int i = 0; i < 8; i++) {
        int r = r0 + i;
        s_rep[i][tid] = (r < RNUM) ? reps[r * 256 + tid] : 0.f;
    }
    __syncthreads();

    for (int jj = 0; jj < 64; jj++) {
        int j = w * 64 + jj;
        float part[8];
        #pragma unroll
        for (int rl = 0; rl < 8; rl++) part[rl] = 0.f;
        #pragma unroll
        for (int i2 = 0; i2 < 8; i2++) {
            int k = lane + 32 * i2;
            float wv = negw[j * 256 + k];
            #pragma unroll
            for (int rl = 0; rl < 8; rl++) part[rl] += wv * fabsf(s_rep[rl][k]);
        }
        #pragma unroll
        for (int off = 16; off > 0; off >>= 1) {
            #pragma unroll
            for (int rl = 0; rl < 8; rl++)
                part[rl] += __shfl_xor_sync(0xffffffffu, part[rl], off);
        }
        if (lane < 8) s_off[lane][j] = part[lane] + negb[j];
    }
    __syncthreads();

    #pragma unroll
    for (int pi = 0; pi < 2; pi++) {
        int pair = w + pi * 8;
        int i = pair & 7, m = pair >> 3;
        float vals[8];
        float ss = 0.f;
        #pragma unroll
        for (int q = 0; q < 8; q++) {
            int e = lane + 32 * q;
            float rv = s_rep[i][e];
            float sg = (rv > 0.f ? 1.f : 0.f) - (rv < 0.f ? 1.f : 0.f);
            float v = (s_off[i][m * 256 + e] + fabsf(rv)) * sg;
            vals[q] = v;
            ss += v * v;
        }
        #pragma unroll
        for (int off = 16; off > 0; off >>= 1) ss += __shfl_xor_sync(0xffffffffu, ss, off);
        float inv = 1.f / fmaxf(sqrtf(ss), 1e-12f);
        int r = r0 + i;
        int t = r >> 5, rl = r & 31;
        size_t rowb = ((size_t)(t * NCOLS + (1 + m) * 32 + rl)) * EK;
        #pragma unroll
        for (int q = 0; q < 8; q++) {
            int e = lane + 32 * q;
            float f = vals[q] * inv;
            __nv_bfloat16 hb = __float2bfloat16(f);
            float lof = f - __bfloat162float(hb);
            g_B[rowb + e]       = hb;
            g_B[rowb + 256 + e] = hb;
            g_B[rowb + 512 + e] = __float2bfloat16(lof);
        }
    }
    #pragma unroll
    for (int i = 0; i < 8; i++) {
        int r = r0 + i;
        int t = r >> 5, rl = r & 31;
        float f = s_rep[i][tid];
        __nv_bfloat16 hb = __float2bfloat16(f);
        float lof = f - __bfloat162float(hb);
        size_t rowb = ((size_t)(t * NCOLS + rl)) * EK + tid;
        g_B[rowb]       = hb;
        g_B[rowb + 256] = hb;
        g_B[rowb + 512] = __float2bfloat16(lof);
    }
}

// =====================================================================
// Kernel 2: 1x1 conv + bias + L2 normalize; writes split-bf16 A'.
// =====================================================================
__global__ __launch_bounds__(256) void conv_norm_kernel(
    const float* __restrict__ x,
    const float* __restrict__ W,
    const float* __restrict__ bias)
{
    __shared__ float sA[16 * 64];
    __shared__ float sB[16 * 260];
    __shared__ float sbias[256];

    const int t = threadIdx.x;
    const int tx = t & 31, ty = t >> 5;
    const int p0 = blockIdx.x * 64;
    const int bimg = p0 >> 12;
    const int hw0 = p0 & 4095;

    sbias[t] = bias[t];

    unsigned long long acc[4][8];
    #pragma unroll
    for (int i = 0; i < 4; i++)
        #pragma unroll
        for (int e = 0; e < 8; e++) acc[i][e] = 0ull;

    const int pxl = t & 63, kb = t >> 6;
    const int kk = t & 15, eb = t >> 4;

    float rxA[4], rxB[16];
    #pragma unroll
    for (int i = 0; i < 4; i++)
        rxA[i] = x[((size_t)bimg * 256 + (kb + 4 * i)) * 4096 + hw0 + pxl];
    #pragma unroll
    for (int i = 0; i < 16; i++)
        rxB[i] = W[(size_t)(eb + 16 * i) * 256 + kk];

    for (int c0 = 0; c0 < 256; c0 += 16) {
        __syncthreads();
        #pragma unroll
        for (int i = 0; i < 4; i++) sA[(kb + 4 * i) * 64 + pxl] = rxA[i];
        #pragma unroll
        for (int i = 0; i < 16; i++) sB[kk * 260 + eb + 16 * i] = rxB[i];
        __syncthreads();
        if (c0 + 16 < 256) {
            int c1 = c0 + 16;
            #pragma unroll
            for (int i = 0; i < 4; i++)
                rxA[i] = x[((size_t)bimg * 256 + c1 + (kb + 4 * i)) * 4096 + hw0 + pxl];
            #pragma unroll
            for (int i = 0; i < 16; i++)
                rxB[i] = W[(size_t)(eb + 16 * i) * 256 + c1 + kk];
        }
        #pragma unroll
        for (int k = 0; k < 16; k++) {
            const float* sak = &sA[k * 64 + ty * 8];
            unsigned long long a0 = *(const unsigned long long*)(sak + 0);
            unsigned long long a1 = *(const unsigned long long*)(sak + 2);
            unsigned long long a2 = *(const unsigned long long*)(sak + 4);
            unsigned long long a3 = *(const unsigned long long*)(sak + 6);
            const float* sbk = &sB[k * 260 + tx * 8];
            float4 bv0 = *(const float4*)(sbk);
            float4 bv1 = *(const float4*)(sbk + 4);
            float bf[8] = {bv0.x, bv0.y, bv0.z, bv0.w, bv1.x, bv1.y, bv1.z, bv1.w};
            #pragma unroll
            for (int e = 0; e < 8; e++) {
                unsigned long long d = f2_pack(bf[e], bf[e]);
                f2_fma(acc[0][e], a0, d);
                f2_fma(acc[1][e], a1, d);
                f2_fma(acc[2][e], a2, d);
                f2_fma(acc[3][e], a3, d);
            }
        }
    }

    float v[8][8];
    #pragma unroll
    for (int i = 0; i < 4; i++)
        #pragma unroll
        for (int e = 0; e < 8; e++)
            f2_unpack(acc[i][e], v[2 * i][e], v[2 * i + 1][e]);
    #pragma unroll
    for (int pp = 0; pp < 8; pp++)
        #pragma unroll
        for (int e = 0; e < 8; e++) v[pp][e] += sbias[tx * 8 + e];

    float part[8];
    #pragma unroll
    for (int pp = 0; pp < 8; pp++) {
        float s = 0.f;
        #pragma unroll
        for (int e = 0; e < 8; e++) s += v[pp][e] * v[pp][e];
        part[pp] = s;
    }
    #pragma unroll
    for (int off = 16; off > 0; off >>= 1)
        #pragma unroll
        for (int pp = 0; pp < 8; pp++)
            part[pp] += __shfl_xor_sync(0xffffffffu, part[pp], off);

    #pragma unroll
    for (int pp = 0; pp < 8; pp++) {
        float inv = 1.f / fmaxf(sqrtf(part[pp]), 1e-12f);
        __nv_bfloat16 h[8]; float lo[8];
        #pragma unroll
        for (int e = 0; e < 8; e++) {
            float f = v[pp][e] * inv;
            h[e] = __float2bfloat16(f);
            lo[e] = f - __bfloat162float(h[e]);
        }
        uint4 uh, ul;
        uh.x = pk_bf2(h[0], h[1]); uh.y = pk_bf2(h[2], h[3]);
        uh.z = pk_bf2(h[4], h[5]); uh.w = pk_bf2(h[6], h[7]);
        ul.x = pk_bf2(__float2bfloat16(lo[0]), __float2bfloat16(lo[1]));
        ul.y = pk_bf2(__float2bfloat16(lo[2]), __float2bfloat16(lo[3]));
        ul.z = pk_bf2(__float2bfloat16(lo[4]), __float2bfloat16(lo[5]));
        ul.w = pk_bf2(__float2bfloat16(lo[6]), __float2bfloat16(lo[7]));
        size_t rowb = (size_t)(p0 + ty * 8 + pp) * EK + tx * 8;
        *(uint4*)&g_embA[rowb]       = uh;   // hi
        *(uint4*)&g_embA[rowb + 256] = ul;   // lo
        *(uint4*)&g_embA[rowb + 512] = uh;   // hi
    }
}

// =====================================================================
// Kernel 3: bf16 mma.sync GEMM (128px x 96col, K=768) + fused epilogue.
// grid (512, 12) x 256 threads (8 warps: 4m x 2n, warp tile 32x48).
// =====================================================================
#define SMA(buf) ((buf) ? 16384 : 0)
#define SMB(buf) (32768 + ((buf) ? 12288 : 0))
#define CSTRIDE 129
#define SUMBUF_OFF 49536          // after C (96*129*4)
#define SMEM_TOT 57344

__global__ __launch_bounds__(256) void dml_main_kernel(float* __restrict__ out)
{
    extern __shared__ char smem[];
    const uint32_t sbase = smem_u32(smem);
    const int tid = threadIdx.x;
    const int lane = tid & 31;
    const int wid = tid >> 5;
    const int warp_m = wid & 3;
    const int warp_n = wid >> 2;
    const int p0 = (int)blockIdx.x * MPX;
    const int rt = (int)blockIdx.y;
    const int r1 = rt * NT_R;
    const int bimg = p0 >> 12;
    const int hw0 = p0 & 4095;

    const __nv_bfloat16* abase = g_embA + (size_t)p0 * EK;
    const __nv_bfloat16* bbase = g_B + (size_t)rt * NCOLS * EK;

    float acc[2][6][4];
    #pragma unroll
    for (int mt = 0; mt < 2; mt++)
        #pragma unroll
        for (int j = 0; j < 6; j++)
            #pragma unroll
            for (int q = 0; q < 4; q++) acc[mt][j][q] = 0.f;

    uint4 va[4], vb[3];
    // prologue: chunk 0
    #pragma unroll
    for (int i = 0; i < 4; i++) {
        int idx = tid + 256 * i, row = idx >> 3, c = idx & 7;
        va[i] = *((const uint4*)(abase + (size_t)row * EK) + c);
    }
    #pragma unroll
    for (int i = 0; i < 3; i++) {
        int idx = tid + 256 * i, row = idx >> 3, c = idx & 7;
        vb[i] = *((const uint4*)(bbase + (size_t)row * EK) + c);
    }

    for (int s = 0; s < 12; s++) {
        const int buf = s & 1;
        char* sa = smem + SMA(buf);
        char* sb = smem + SMB(buf);
        #pragma unroll
        for (int i = 0; i < 4; i++) {
            int idx = tid + 256 * i, row = idx >> 3, c = idx & 7;
            *(uint4*)(sa + (((row << 3) + (c ^ (row & 7))) << 4)) = va[i];
        }
        #pragma unroll
        for (int i = 0; i < 3; i++) {
            int idx = tid + 256 * i, row = idx >> 3, c = idx & 7;
            *(uint4*)(sb + (((row << 3) + (c ^ (row & 7))) << 4)) = vb[i];
        }
        __syncthreads();

        if (s < 11) {
            const int k0 = (s + 1) * 64;
            #pragma unroll
            for (int i = 0; i < 4; i++) {
                int idx = tid + 256 * i, row = idx >> 3, c = idx & 7;
                va[i] = *((const uint4*)(abase + (size_t)row * EK + k0) + c);
            }
            #pragma unroll
            for (int i = 0; i < 3; i++) {
                int idx = tid + 256 * i, row = idx >> 3, c = idx & 7;
                vb[i] = *((const uint4*)(bbase + (size_t)row * EK + k0) + c);
            }
        }

        const uint32_t saA = sbase + SMA(buf);
        const uint32_t saB = sbase + SMB(buf);
        #pragma unroll
        for (int kk = 0; kk < 4; kk++) {
            uint32_t af[2][4];
            #pragma unroll
            for (int mt = 0; mt < 2; mt++) {
                int row = warp_m * 32 + mt * 16 + (lane & 15);
                int c = kk * 2 + (lane >> 4);
                uint32_t addr = saA + (((row << 3) + (c ^ (row & 7))) << 4);
                LDSM_X4(af[mt][0], af[mt][1], af[mt][2], af[mt][3], addr);
            }
            uint32_t bf[3][4];
            #pragma unroll
            for (int bp = 0; bp < 3; bp++) {
                int row = warp_n * 48 + bp * 16 + ((lane >> 4) << 3) + (lane & 7);
                int c = kk * 2 + ((lane >> 3) & 1);
                uint32_t addr = saB + (((row << 3) + (c ^ (row & 7))) << 4);
                LDSM_X4(bf[bp][0], bf[bp][1], bf[bp][2], bf[bp][3], addr);
            }
            #pragma unroll
            for (int mt = 0; mt < 2; mt++) {
                #pragma unroll
                for (int bp = 0; bp < 3; bp++) {
                    MMA_BF16(acc[mt][bp * 2 + 0], af[mt], bf[bp][0], bf[bp][1]);
                    MMA_BF16(acc[mt][bp * 2 + 1], af[mt], bf[bp][2], bf[bp][3]);
                }
            }
        }
        __syncthreads();
    }

    // -------- stage C to smem --------
    float* Cf = (float*)smem;
    #pragma unroll
    for (int mt = 0; mt < 2; mt++) {
        #pragma unroll
        for (int j = 0; j < 6; j++) {
            int row = warp_m * 32 + mt * 16 + (lane >> 2);
            int col = warp_n * 48 + j * 8 + 2 * (lane & 3);
            Cf[col * CSTRIDE + row]           = acc[mt][j][0];
            Cf[(col + 1) * CSTRIDE + row]     = acc[mt][j][1];
            Cf[col * CSTRIDE + row + 8]       = acc[mt][j][2];
            Cf[(col + 1) * CSTRIDE + row + 8] = acc[mt][j][3];
        }
    }
    __syncthreads();

    // -------- epilogue: thread -> (px = tid&127, r-group = tid>>7) --------
    const int px = tid & 127;
    const int rg = tid >> 7;
    const int hw = hw0 + px;
    const size_t oimg = (size_t)bimg * RNUM;
    float ssum = 0.f;

    #pragma unroll
    for (int pass = 0; pass < 16; pass++) {
        int rloc = pass * 2 + rg;
        int r = r1 + rloc;
        if (r < RNUM) {
            float dp = Cf[rloc * CSTRIDE + px];
            float d0 = Cf[(32 + rloc) * CSTRIDE + px];
            float d1 = Cf[(64 + rloc) * CSTRIDE + px];
            float dp2 = fmaxf(2.f - 2.f * dp, 0.f);
            float d02 = fmaxf(2.f - 2.f * d0, 0.f);
            float d12 = fmaxf(2.f - 2.f * d1, 0.f);
            float dmin2 = fminf(d02, d12);
            float dpl = dp2 * rsqrtf(fmaxf(dp2, 1e-30f));
            float d0l = d02 * rsqrtf(fmaxf(d02, 1e-30f));
            float d1l = d12 * rsqrtf(fmaxf(d12, 1e-30f));
            float dminl = fminf(d0l, d1l);
            float fcn = __expf(-2.f * dmin2);
            float fpo = __expf(-2.f * dp2);
            float tt = dpl + 0.3f * (2.f - dminl);
            float fpr = __expf(-2.f * tt * tt);

            size_t base = (oimg + r) * HWSZ + hw;
            out[OFF_DIST + base]   = dpl;
            out[OFF_CLS + base]    = fpr;
            out[OFF_CLSNEG + base] = fcn;
            out[OFF_PORI + base]   = fpo;
            size_t bn = (oimg + r) * 2 * HWSZ + hw;
            out[OFF_DNEG + bn]        = d0l;
            out[OFF_DNEG + bn + HWSZ] = d1l;
            ssum += fpr;
        }
    }

    __syncthreads();
    float* sumbuf = (float*)(smem + SUMBUF_OFF);
    sumbuf[tid] = ssum;
    __syncthreads();
    if (tid < 128)
        g_part[rt][p0 + tid] = sumbuf[tid] + sumbuf[tid + 128];
}

// =====================================================================
// Kernel 4: combine partials -> 1/sum
// =====================================================================
__global__ __launch_bounds__(256) void inv_sum_kernel()
{
    int i = blockIdx.x * 256 + threadIdx.x;
    float s = 0.f;
    #pragma unroll
    for (int t = 0; t < NTILES; t++) s += g_part[t][i];
    g_sum[i] = 1.f / s;
}

// =====================================================================
// Kernel 5: cls_score *= 1/sum
// =====================================================================
__global__ __launch_bounds__(256) void scale_cls_kernel(float* __restrict__ out)
{
    int row = blockIdx.y;                 // b*RNUM + r
    int b = row / RNUM;
    int hw = blockIdx.x * 1024 + threadIdx.x * 4;
    float4 s = *(float4*)&g_sum[b * 4096 + hw];
    float4 v = *(float4*)&out[OFF_CLS + (size_t)row * HWSZ + hw];
    v.x *= s.x; v.y *= s.y; v.z *= s.z; v.w *= s.w;
    *(float4*)&out[OFF_CLS + (size_t)row * HWSZ + hw] = v;
}

// =====================================================================
extern "C" void kernel_launch(void* const* d_in, const int* in_sizes, int n_in,
                              void* d_out, int out_size)
{
    (void)in_sizes; (void)n_in; (void)out_size;
    const float* x      = (const float*)d_in[0];
    const float* conv_w = (const float*)d_in[1];
    const float* conv_b = (const float*)d_in[2];
    const float* reps   = (const float*)d_in[3];
    const float* neg_w  = (const float*)d_in[4];
    const float* neg_b  = (const float*)d_in[5];
    float* out = (float*)d_out;

    cudaFuncSetAttribute(dml_main_kernel,
                         cudaFuncAttributeMaxDynamicSharedMemorySize, SMEM_TOT);

    prep_reps_kernel<<<48, 256>>>(reps, neg_w, neg_b);
    conv_norm_kernel<<<1024, 256>>>(x, conv_w, conv_b);
    dml_main_kernel<<<dim3(512, NTILES), 256, SMEM_TOT>>>(out);
    inv_sum_kernel<<<256, 256>>>();
    scale_cls_kernel<<<dim3(4, BATCH * RNUM), 256>>>(out);
}